// round 8
// baseline (speedup 1.0000x reference)
#include <cuda_runtime.h>

#define EPSF 1e-7f
#define ACLIPF (1.0f - 1e-6f)
#define PI_F 3.14159274101257324f
#define PI_HALF_F 1.57079637050628662f

// Scratch for deterministic single-launch reduction (no device allocs allowed).
static __device__ float g_partials[8192];
static __device__ unsigned int g_ticket = 0;   // self-resetting via atomicInc wrap

__device__ __forceinline__ float fsqrt_approx(float x) {   // single MUFU.SQRT
    float r; asm("sqrt.approx.f32 %0, %1;" : "=f"(r) : "f"(x)); return r;
}

// acos approximation for x in [0,1): abs err <= ~6.8e-5
__device__ __forceinline__ float facos_pos(float x) {
    float p = fmaf(x, -0.0187293f, 0.0742610f);
    p = fmaf(x, p, -0.2121144f);
    p = fmaf(x, p, 1.5707288f);
    return fsqrt_approx(1.0f - x) * p;   // 1-x >= 1e-6 after clipping
}

// acos for x in (-1,1), branchless: acos(x) = off + s*acos_pos(|x|)
// with s = copysign(1,x), off = pi/2*(1-s)  (0 for x>=0, pi for x<0)
__device__ __forceinline__ float facos(float x) {
    float v = facos_pos(fabsf(x));
    float s = copysignf(1.0f, x);
    float off = fmaf(s, -PI_HALF_F, PI_HALF_F);
    return fmaf(s, v, off);
}

// Branchless circle-GIoU: the clipped-acos lens formula saturates to the
// contained / disjoint values of inter and hull, so NO predicates or selects.
__device__ __forceinline__ float giou_loss(float cx0, float cy0, float r0,
                                           float cx1, float cy1, float r1) {
    float dx = cx0 - cx1, dy = cy0 - cy1;
    float d2 = fmaf(dx, dx, dy * dy);
    float d2c = fmaxf(d2, EPSF);
    float inv_d = rsqrtf(d2c);

    float r0s = r0 * r0, r1s = r1 * r1;
    float e = r0s - r1s;                 // r0^2 - r1^2
    float rsum  = r0 + r1;
    float rdiff = fabsf(r0 - r1);
    float rsum2  = rsum * rsum;
    float rdiff2 = rdiff * rdiff;
    float ae = rsum * rdiff;             // |r0^2 - r1^2|

    // cos0 = (d2+e)/(2 d r0), cos1 = (d2-e)/(2 d r1); saturating clips
    float half_invd = 0.5f * inv_d;
    float cos0 = __fdividef((d2 + e) * half_invd, r0);
    cos0 = fminf(fmaxf(cos0, -ACLIPF), ACLIPF);
    float acos0 = facos(cos0);
    float cos1 = __fdividef((d2 - e) * half_invd, r1);
    cos1 = fminf(fmaxf(cos1, -ACLIPF), ACLIPF);
    float acos1 = facos(cos1);

    // t = (rsum^2 - d^2)(d^2 - rdiff^2) > 0 exactly in the lens region
    float sqrt_t = fsqrt_approx(fmaxf((rsum2 - d2c) * (d2c - rdiff2), EPSF));
    // unconditional inter: saturates to pi*rmin^2 (contained) / 0 (disjoint)
    float inter = fmaf(r0s, acos0, fmaf(r1s, acos1, -0.5f * sqrt_t));

    float uni = fmaf(PI_F, r0s + r1s, -inter);

    // unconditional hull: alpha saturates so hull -> pi*rmax^2 when contained
    float alpha = facos_pos(fminf(rdiff * inv_d, ACLIPF));
    float sqrt_h2 = fsqrt_approx(fmaxf(d2 - rdiff2, EPSF));
    float hull = fmaf(rsum, sqrt_h2,
                 fmaf(alpha, -ae, PI_F * fmaxf(r0s, r1s)));

    // loss = 1 - (inter/U - (hull-uni)/H) with a single divide
    float U = fmaxf(uni, EPSF), H = fmaxf(hull, EPSF);
    float num = fmaf(inter, H, -(hull - uni) * U);
    return 1.0f - __fdividef(num, U * H);
}

// Persistent kernel: exactly one resident wave (148 SMs x 8 blocks = 1184),
// grid-stride over quads (4 elems / thread / iter via 3 float4 loads each side).
// __launch_bounds__(256, 8): cap at 32 regs -> 2048 threads/SM resident.
__global__ void __launch_bounds__(256, 8) giou_fused_kernel(
    const float* __restrict__ x, const float* __restrict__ y,
    float* __restrict__ out, int n) {
    int quads = (n + 3) >> 2;
    int stride = gridDim.x * 256;
    float acc = 0.0f;

    for (int quad = blockIdx.x * 256 + threadIdx.x; quad < quads; quad += stride) {
        int base = quad * 4;
        if (base + 3 < n) {
            const float4* x4 = (const float4*)x;
            const float4* y4 = (const float4*)y;
            float4 xa = x4[quad * 3 + 0];
            float4 ya = y4[quad * 3 + 0];
            float4 xb = x4[quad * 3 + 1];
            float4 yb = y4[quad * 3 + 1];
            float4 xc = x4[quad * 3 + 2];
            float4 yc = y4[quad * 3 + 2];
            acc += giou_loss(xa.x, xa.y, xa.z, ya.x, ya.y, ya.z);
            acc += giou_loss(xa.w, xb.x, xb.y, ya.w, yb.x, yb.y);
            acc += giou_loss(xb.z, xb.w, xc.x, yb.z, yb.w, yc.x);
            acc += giou_loss(xc.y, xc.z, xc.w, yc.y, yc.z, yc.w);
        } else {
            for (int i = base; i < n; i++) {
                acc += giou_loss(x[3*i], x[3*i+1], x[3*i+2],
                                 y[3*i], y[3*i+1], y[3*i+2]);
            }
        }
    }

    // block reduce
    #pragma unroll
    for (int off = 16; off > 0; off >>= 1)
        acc += __shfl_xor_sync(0xFFFFFFFFu, acc, off);

    __shared__ float warp_sums[8];
    __shared__ bool amLast;
    int lane = threadIdx.x & 31;
    int wid  = threadIdx.x >> 5;
    if (lane == 0) warp_sums[wid] = acc;
    __syncthreads();
    if (wid == 0) {
        float v = (lane < 8) ? warp_sums[lane] : 0.0f;
        #pragma unroll
        for (int off = 4; off > 0; off >>= 1)
            v += __shfl_xor_sync(0xFFFFFFFFu, v, off);
        if (lane == 0) {
            g_partials[blockIdx.x] = v;
            __threadfence();
            unsigned int t = atomicInc(&g_ticket, gridDim.x - 1); // wraps to 0 on last
            amLast = (t == gridDim.x - 1);
        }
    }
    __syncthreads();

    if (amLast) {
        __threadfence();
        int nblocks = gridDim.x;
        float a2 = 0.0f;
        for (int i = threadIdx.x; i < nblocks; i += 256)
            a2 += g_partials[i];                      // fixed order -> deterministic
        #pragma unroll
        for (int off = 16; off > 0; off >>= 1)
            a2 += __shfl_xor_sync(0xFFFFFFFFu, a2, off);
        __syncthreads();                              // reuse warp_sums safely
        if (lane == 0) warp_sums[wid] = a2;
        __syncthreads();
        if (wid == 0) {
            float v = (lane < 8) ? warp_sums[lane] : 0.0f;
            #pragma unroll
            for (int off = 4; off > 0; off >>= 1)
                v += __shfl_xor_sync(0xFFFFFFFFu, v, off);
            if (lane == 0) out[0] = v;
        }
    }
}

extern "C" void kernel_launch(void* const* d_in, const int* in_sizes, int n_in,
                              void* d_out, int out_size) {
    const float* x = (const float*)d_in[0];
    const float* y = (const float*)d_in[1];
    int n = in_sizes[0] / 3;                 // number of circle pairs
    int quads = (n + 3) / 4;
    // One full resident wave on GB300: 148 SMs x 8 blocks/SM.
    int blocks = 148 * 8;                    // 1184
    int needed = (quads + 255) / 256;        // don't over-launch tiny inputs
    if (blocks > needed) blocks = needed;
    if (blocks < 1) blocks = 1;

    giou_fused_kernel<<<blocks, 256>>>(x, y, (float*)d_out, n);
}

// round 9
// speedup vs baseline: 1.0426x; 1.0426x over previous
#include <cuda_runtime.h>

#define EPSF 1e-7f
#define ACLIPF (1.0f - 1e-6f)
#define PI_F 3.14159274101257324f
#define PI_HALF_F 1.57079637050628662f

// Scratch for deterministic single-launch reduction (no device allocs allowed).
static __device__ float g_partials[8192];
static __device__ unsigned int g_ticket = 0;   // self-resetting via atomicInc wrap

__device__ __forceinline__ float fsqrt_approx(float x) {   // single MUFU.SQRT
    float r; asm("sqrt.approx.f32 %0, %1;" : "=f"(r) : "f"(x)); return r;
}

// acos approximation for x in [0,1): abs err <= ~6.8e-5
__device__ __forceinline__ float facos_pos(float x) {
    float p = fmaf(x, -0.0187293f, 0.0742610f);
    p = fmaf(x, p, -0.2121144f);
    p = fmaf(x, p, 1.5707288f);
    return fsqrt_approx(1.0f - x) * p;   // 1-x >= 1e-6 after clipping
}

// acos for x in (-1,1), branchless: acos(x) = off + s*acos_pos(|x|)
__device__ __forceinline__ float facos(float x) {
    float v = facos_pos(fabsf(x));
    float s = copysignf(1.0f, x);
    float off = fmaf(s, -PI_HALF_F, PI_HALF_F);
    return fmaf(s, v, off);
}

// Branchless circle-GIoU: the clipped-acos lens formula saturates to the
// contained / disjoint values of inter and hull, so NO predicates or selects.
__device__ __forceinline__ float giou_loss(float cx0, float cy0, float r0,
                                           float cx1, float cy1, float r1) {
    float dx = cx0 - cx1, dy = cy0 - cy1;
    float d2 = fmaf(dx, dx, dy * dy);
    float d2c = fmaxf(d2, EPSF);
    float inv_d = rsqrtf(d2c);

    float r0s = r0 * r0, r1s = r1 * r1;
    float e = r0s - r1s;                 // r0^2 - r1^2
    float rsum  = r0 + r1;
    float rdiff = fabsf(r0 - r1);
    float rsum2  = rsum * rsum;
    float rdiff2 = rdiff * rdiff;
    float ae = rsum * rdiff;             // |r0^2 - r1^2|

    // cos0 = (d2+e)/(2 d r0), cos1 = (d2-e)/(2 d r1); saturating clips
    float half_invd = 0.5f * inv_d;
    float cos0 = __fdividef((d2 + e) * half_invd, r0);
    cos0 = fminf(fmaxf(cos0, -ACLIPF), ACLIPF);
    float acos0 = facos(cos0);
    float cos1 = __fdividef((d2 - e) * half_invd, r1);
    cos1 = fminf(fmaxf(cos1, -ACLIPF), ACLIPF);
    float acos1 = facos(cos1);

    // t = (rsum^2 - d^2)(d^2 - rdiff^2) > 0 exactly in the lens region
    float sqrt_t = fsqrt_approx(fmaxf((rsum2 - d2c) * (d2c - rdiff2), EPSF));
    // unconditional inter: saturates to pi*rmin^2 (contained) / 0 (disjoint)
    float inter = fmaf(r0s, acos0, fmaf(r1s, acos1, -0.5f * sqrt_t));

    float uni = fmaf(PI_F, r0s + r1s, -inter);

    // unconditional hull: alpha saturates so hull -> pi*rmax^2 when contained
    float alpha = facos_pos(fminf(rdiff * inv_d, ACLIPF));
    float sqrt_h2 = fsqrt_approx(fmaxf(d2 - rdiff2, EPSF));
    float hull = fmaf(rsum, sqrt_h2,
                 fmaf(alpha, -ae, PI_F * fmaxf(r0s, r1s)));

    // loss = 2 - (inter/U + uni/H) = 2 - (inter*H + uni*U)/(U*H)
    float U = fmaxf(uni, EPSF), H = fmaxf(hull, EPSF);
    float num = fmaf(inter, H, uni * U);
    return 2.0f - __fdividef(num, U * H);
}

// Single-wave launch: 1024 blocks x 256 threads (262144 threads, all resident
// on 152 SMs at <=7 blocks/SM with 32 regs). Each thread processes QPT quads
// (16 elements) via a stride-coalesced loop; no wave-quantization tail.
// Last block (ticket pattern) folds g_partials -> out[0] in a fixed order.
__global__ void __launch_bounds__(256, 8) giou_fused_kernel(
    const float* __restrict__ x, const float* __restrict__ y,
    float* __restrict__ out, int n) {
    int quads = (n + 3) >> 2;
    int nthreads = gridDim.x * 256;
    float acc = 0.0f;

    const float4* x4 = (const float4*)x;
    const float4* y4 = (const float4*)y;

    #pragma unroll 1
    for (int quad = blockIdx.x * 256 + threadIdx.x; quad < quads; quad += nthreads) {
        int base = quad * 4;
        if (base + 3 < n) {
            float4 xa = x4[quad * 3 + 0];
            float4 ya = y4[quad * 3 + 0];
            float4 xb = x4[quad * 3 + 1];
            float4 yb = y4[quad * 3 + 1];
            float4 xc = x4[quad * 3 + 2];
            float4 yc = y4[quad * 3 + 2];
            acc += giou_loss(xa.x, xa.y, xa.z, ya.x, ya.y, ya.z);
            acc += giou_loss(xa.w, xb.x, xb.y, ya.w, yb.x, yb.y);
            acc += giou_loss(xb.z, xb.w, xc.x, yb.z, yb.w, yc.x);
            acc += giou_loss(xc.y, xc.z, xc.w, yc.y, yc.z, yc.w);
        } else {
            for (int i = base; i < n; i++) {
                acc += giou_loss(x[3*i], x[3*i+1], x[3*i+2],
                                 y[3*i], y[3*i+1], y[3*i+2]);
            }
        }
    }

    // block reduce
    #pragma unroll
    for (int off = 16; off > 0; off >>= 1)
        acc += __shfl_xor_sync(0xFFFFFFFFu, acc, off);

    __shared__ float warp_sums[8];
    __shared__ bool amLast;
    int lane = threadIdx.x & 31;
    int wid  = threadIdx.x >> 5;
    if (lane == 0) warp_sums[wid] = acc;
    __syncthreads();
    if (wid == 0) {
        float v = (lane < 8) ? warp_sums[lane] : 0.0f;
        #pragma unroll
        for (int off = 4; off > 0; off >>= 1)
            v += __shfl_xor_sync(0xFFFFFFFFu, v, off);
        if (lane == 0) {
            g_partials[blockIdx.x] = v;
            __threadfence();
            unsigned int t = atomicInc(&g_ticket, gridDim.x - 1); // wraps to 0 on last
            amLast = (t == gridDim.x - 1);
        }
    }
    __syncthreads();

    if (amLast) {
        __threadfence();
        int nblocks = gridDim.x;
        float a2 = 0.0f;
        for (int i = threadIdx.x; i < nblocks; i += 256)
            a2 += g_partials[i];                      // fixed order -> deterministic
        #pragma unroll
        for (int off = 16; off > 0; off >>= 1)
            a2 += __shfl_xor_sync(0xFFFFFFFFu, a2, off);
        __syncthreads();                              // reuse warp_sums safely
        if (lane == 0) warp_sums[wid] = a2;
        __syncthreads();
        if (wid == 0) {
            float v = (lane < 8) ? warp_sums[lane] : 0.0f;
            #pragma unroll
            for (int off = 4; off > 0; off >>= 1)
                v += __shfl_xor_sync(0xFFFFFFFFu, v, off);
            if (lane == 0) out[0] = v;
        }
    }
}

extern "C" void kernel_launch(void* const* d_in, const int* in_sizes, int n_in,
                              void* d_out, int out_size) {
    const float* x = (const float*)d_in[0];
    const float* y = (const float*)d_in[1];
    int n = in_sizes[0] / 3;                 // number of circle pairs
    int quads = (n + 3) / 4;
    // Single resident wave: 1024 blocks (<= 7 blocks/SM on 152 SMs at 32 regs),
    // each thread handles 4 quads = 16 elements for N=4194304.
    int blocks = 1024;
    int needed = (quads + 255) / 256;        // don't over-launch tiny inputs
    if (blocks > needed) blocks = needed;
    if (blocks < 1) blocks = 1;
    if (blocks > 8192) blocks = 8192;        // g_partials capacity

    giou_fused_kernel<<<blocks, 256>>>(x, y, (float*)d_out, n);
}